// round 11
// baseline (speedup 1.0000x reference)
#include <cuda_runtime.h>
#include <cuda_fp16.h>
#include <math_constants.h>

// ---------------------------------------------------------------------------
// 2-layer GCN collapsed to scalar graph ops (feature dims 1 -> H -> 1).
//   deg[v] = #in-edges + 1 ; dis[v] = rsqrt(deg[v])
//   s1[v]  = dis[v] * ( sum_{u->v} dis[u]*x[u] + dis[v]*x[v] )
//   t[v]   = PW(s1[v])  (piecewise-linear collapse of relu-MLP)
//   out[v] = dis[v] * ( sum_{u->v} dis[u]*t[u] + dis[v]*t[v] ) + b2
// Scatter passes: persistent blocks stage the whole 196KB fp16 message array
// in shared memory, gather via LDS (smem crossbar) so the L1tex wavefront
// queue serves only the REDG atomics. Index loads __ldcg (L2-resident).
// g_deg zero-invariant maintained by nodeA; prep rides on the deg launch.
// ---------------------------------------------------------------------------

#define MAXN 100352   // >= N_NODES (100000), multiple of 8
#define MAXH 256
#define SMEM_BYTES (MAXN * 2)   // 200704 B fp16 message array

__device__ float  g_deg[MAXN];    // zero at load; invariant: ==0 at call entry
__device__ float  g_dis[MAXN];
__device__ float  g_val[MAXN];    // fp32 message value (self-term use)
__device__ __half g_valh[MAXN];   // fp16 copy, staged to smem in scatter
__device__ float  g_acc[MAXN];    // scatter accumulator (fp32)

__device__ float g_pw_c[MAXH];      // sorted breakpoints
__device__ float g_pw_A[MAXH + 1];  // segment slopes
__device__ float g_pw_B[MAXH + 1];  // segment intercepts

// ---- piecewise-linear table build (one 256-thread block) -------------------
__device__ void prep_block(const float* __restrict__ W1,
                           const float* __restrict__ b1,
                           const float* __restrict__ W2, int H) {
    __shared__ float sc[MAXH];
    __shared__ float sdA[MAXH], sdB[MAXH];
    __shared__ float sA[MAXH], sB[MAXH];
    __shared__ float s_base[2];

    int i = threadIdx.x;

    float w1 = (i < H) ? W1[i] : 0.0f;
    float bb = (i < H) ? b1[i] : 0.0f;
    float w2 = (i < H) ? W2[i] : 0.0f;
    float aa = w1 * w2;
    float cc = bb * w2;

    float key, dA, dB;
    float base_A = 0.0f, base_B = 0.0f;
    if (i < H && w1 > 0.0f) {
        key = -bb / w1; dA = aa;  dB = cc;
    } else if (i < H && w1 < 0.0f) {
        key = -bb / w1; dA = -aa; dB = -cc;
        base_A = aa; base_B = cc;
    } else {
        key = CUDART_INF_F; dA = 0.0f; dB = 0.0f;
        if (i < H && bb > 0.0f) base_B = cc;
    }
    sc[i] = key; sdA[i] = dA; sdB[i] = dB;
    sA[i] = base_A; sB[i] = base_B;
    __syncthreads();

    for (int off = MAXH / 2; off > 0; off >>= 1) {
        if (i < off) { sA[i] += sA[i + off]; sB[i] += sB[i + off]; }
        __syncthreads();
    }
    if (i == 0) { s_base[0] = sA[0]; s_base[1] = sB[0]; }
    __syncthreads();

    for (int k = 2; k <= MAXH; k <<= 1) {
        for (int j = k >> 1; j > 0; j >>= 1) {
            int ixj = i ^ j;
            if (ixj > i) {
                bool up = ((i & k) == 0);
                if ((sc[i] > sc[ixj]) == up) {
                    float tk = sc[i];  sc[i]  = sc[ixj];  sc[ixj]  = tk;
                    float ta = sdA[i]; sdA[i] = sdA[ixj]; sdA[ixj] = ta;
                    float tb = sdB[i]; sdB[i] = sdB[ixj]; sdB[ixj] = tb;
                }
            }
            __syncthreads();
        }
    }

    float pa = sdA[i], pb = sdB[i];
    sA[i] = pa; sB[i] = pb;
    __syncthreads();
    for (int off = 1; off < MAXH; off <<= 1) {
        float na = sA[i], nb = sB[i];
        if (i >= off) { na += sA[i - off]; nb += sB[i - off]; }
        __syncthreads();
        sA[i] = na; sB[i] = nb;
        __syncthreads();
    }

    g_pw_c[i] = sc[i];
    g_pw_A[i + 1] = s_base[0] + sA[i];
    g_pw_B[i + 1] = s_base[1] + sB[i];
    if (i == 0) { g_pw_A[0] = s_base[0]; g_pw_B[0] = s_base[1]; }
}

// ---- degree pass + prep rider; __ldcg index loads ---------------------------
__global__ void k_deg4(const int* __restrict__ dst, int E,
                       const float* __restrict__ W1,
                       const float* __restrict__ b1,
                       const float* __restrict__ W2, int H) {
    if (blockIdx.x == gridDim.x - 1) {      // prep rider block
        prep_block(W1, b1, W2, H);
        return;
    }
    int i = (blockIdx.x * blockDim.x + threadIdx.x) * 4;
    if (i + 3 < E) {
        int4 d = __ldcg(reinterpret_cast<const int4*>(dst + i));
        atomicAdd(&g_deg[d.x], 1.0f);
        atomicAdd(&g_deg[d.y], 1.0f);
        atomicAdd(&g_deg[d.z], 1.0f);
        atomicAdd(&g_deg[d.w], 1.0f);
    } else {
        for (; i < E; ++i) atomicAdd(&g_deg[__ldcg(dst + i)], 1.0f);
    }
}

// ---- scatter: persistent blocks, message array staged in smem ---------------
// Gather = LDS (smem crossbar); atomic = REDG (L1tex/L2). Pipes overlap.
__global__ void __launch_bounds__(1024, 1)
k_edge_smem(const int* __restrict__ src, const int* __restrict__ dst, int E) {
    extern __shared__ __half sval[];

    // cooperative stage: 196KB, int4-vectorized (8 halves per load)
    const int4* gv = reinterpret_cast<const int4*>(g_valh);
    int4* sv = reinterpret_cast<int4*>(sval);
    #pragma unroll 4
    for (int i = threadIdx.x; i < MAXN / 8; i += 1024)
        sv[i] = __ldg(&gv[i]);
    __syncthreads();

    int stride = gridDim.x * blockDim.x * 4;
    for (int i = (blockIdx.x * blockDim.x + threadIdx.x) * 4; i < E; i += stride) {
        if (i + 3 < E) {
            int4 s = __ldcg(reinterpret_cast<const int4*>(src + i));
            int4 d = __ldcg(reinterpret_cast<const int4*>(dst + i));
            float v0 = __half2float(sval[s.x]);
            float v1 = __half2float(sval[s.y]);
            float v2 = __half2float(sval[s.z]);
            float v3 = __half2float(sval[s.w]);
            atomicAdd(&g_acc[d.x], v0);
            atomicAdd(&g_acc[d.y], v1);
            atomicAdd(&g_acc[d.z], v2);
            atomicAdd(&g_acc[d.w], v3);
        } else {
            for (int j = i; j < E; ++j)
                atomicAdd(&g_acc[__ldcg(dst + j)],
                          __half2float(sval[__ldcg(src + j)]));
        }
    }
}

// ---- node kernels, 4 nodes/thread -------------------------------------------
__global__ void k_nodeA(const float* __restrict__ x, int n) {
    int t = blockIdx.x * blockDim.x + threadIdx.x;
    int v = t * 4;
    if (v + 3 < n) {
        float4 dg = *reinterpret_cast<float4*>(&g_deg[v]);
        float4 xx = *reinterpret_cast<const float4*>(&x[v]);
        float4 d, val;
        d.x = rsqrtf(dg.x + 1.0f); d.y = rsqrtf(dg.y + 1.0f);
        d.z = rsqrtf(dg.z + 1.0f); d.w = rsqrtf(dg.w + 1.0f);
        val.x = d.x * xx.x; val.y = d.y * xx.y;
        val.z = d.z * xx.z; val.w = d.w * xx.w;
        *reinterpret_cast<float4*>(&g_deg[v]) = make_float4(0.f, 0.f, 0.f, 0.f);
        *reinterpret_cast<float4*>(&g_dis[v]) = d;
        *reinterpret_cast<float4*>(&g_val[v]) = val;
        *reinterpret_cast<__half2*>(&g_valh[v])     = __floats2half2_rn(val.x, val.y);
        *reinterpret_cast<__half2*>(&g_valh[v + 2]) = __floats2half2_rn(val.z, val.w);
        *reinterpret_cast<float4*>(&g_acc[v]) = make_float4(0.f, 0.f, 0.f, 0.f);
    } else {
        for (; v < n; ++v) {
            float d = rsqrtf(g_deg[v] + 1.0f);
            g_deg[v] = 0.0f;
            float val = d * x[v];
            g_dis[v] = d;
            g_val[v] = val;
            g_valh[v] = __float2half_rn(val);
            g_acc[v] = 0.0f;
        }
    }
}

// nodeB: 4 interleaved binary searches/thread
__global__ void k_nodeB(int H, int n) {
    __shared__ float sc[MAXH], sA[MAXH + 1], sB[MAXH + 1];
    for (int k = threadIdx.x; k < MAXH; k += blockDim.x) {
        sc[k] = g_pw_c[k];
        sA[k] = g_pw_A[k];
        sB[k] = g_pw_B[k];
    }
    if (threadIdx.x == 0) { sA[MAXH] = g_pw_A[MAXH]; sB[MAXH] = g_pw_B[MAXH]; }
    __syncthreads();
    int t = blockIdx.x * blockDim.x + threadIdx.x;
    int v = t * 4;
    if (v + 3 < n) {
        float4 d   = *reinterpret_cast<float4*>(&g_dis[v]);
        float4 ac  = *reinterpret_cast<float4*>(&g_acc[v]);
        float4 vl  = *reinterpret_cast<float4*>(&g_val[v]);
        float s[4], dd[4];
        dd[0] = d.x; dd[1] = d.y; dd[2] = d.z; dd[3] = d.w;
        s[0] = d.x * (ac.x + vl.x); s[1] = d.y * (ac.y + vl.y);
        s[2] = d.z * (ac.z + vl.z); s[3] = d.w * (ac.w + vl.w);
        int lo[4] = {0, 0, 0, 0}, hi[4] = {MAXH, MAXH, MAXH, MAXH};
        #pragma unroll
        for (int step = 0; step < 8; ++step) {
            #pragma unroll
            for (int j = 0; j < 4; ++j) {
                int mid = (lo[j] + hi[j]) >> 1;
                if (sc[mid] <= s[j]) lo[j] = mid + 1; else hi[j] = mid;
            }
        }
        float4 val;
        val.x = dd[0] * fmaf(sA[lo[0]], s[0], sB[lo[0]]);
        val.y = dd[1] * fmaf(sA[lo[1]], s[1], sB[lo[1]]);
        val.z = dd[2] * fmaf(sA[lo[2]], s[2], sB[lo[2]]);
        val.w = dd[3] * fmaf(sA[lo[3]], s[3], sB[lo[3]]);
        *reinterpret_cast<float4*>(&g_val[v]) = val;
        *reinterpret_cast<__half2*>(&g_valh[v])     = __floats2half2_rn(val.x, val.y);
        *reinterpret_cast<__half2*>(&g_valh[v + 2]) = __floats2half2_rn(val.z, val.w);
        *reinterpret_cast<float4*>(&g_acc[v]) = make_float4(0.f, 0.f, 0.f, 0.f);
    } else {
        for (; v < n; ++v) {
            float d = g_dis[v];
            float s = d * (g_acc[v] + g_val[v]);
            int lo = 0, hi2 = MAXH;
            #pragma unroll
            for (int step = 0; step < 8; ++step) {
                int mid = (lo + hi2) >> 1;
                if (sc[mid] <= s) lo = mid + 1; else hi2 = mid;
            }
            float val = d * fmaf(sA[lo], s, sB[lo]);
            g_val[v] = val;
            g_valh[v] = __float2half_rn(val);
            g_acc[v] = 0.0f;
        }
    }
}

__global__ void k_nodeC(float* __restrict__ out, const float* __restrict__ b2,
                        int n) {
    int t = blockIdx.x * blockDim.x + threadIdx.x;
    int v = t * 4;
    float bias = b2[0];
    if (v + 3 < n) {
        float4 d  = *reinterpret_cast<float4*>(&g_dis[v]);
        float4 ac = *reinterpret_cast<float4*>(&g_acc[v]);
        float4 vl = *reinterpret_cast<float4*>(&g_val[v]);
        float4 o;
        o.x = fmaf(d.x, ac.x + vl.x, bias);
        o.y = fmaf(d.y, ac.y + vl.y, bias);
        o.z = fmaf(d.z, ac.z + vl.z, bias);
        o.w = fmaf(d.w, ac.w + vl.w, bias);
        *reinterpret_cast<float4*>(&out[v]) = o;
    } else {
        for (; v < n; ++v)
            out[v] = fmaf(g_dis[v], g_acc[v] + g_val[v], bias);
    }
}

extern "C" void kernel_launch(void* const* d_in, const int* in_sizes, int n_in,
                              void* d_out, int out_size) {
    const float* x  = (const float*)d_in[0];
    const int*   ei = (const int*)d_in[1];     // int32 edge indices
    const float* W1 = (const float*)d_in[2];
    const float* b1 = (const float*)d_in[3];
    const float* W2 = (const float*)d_in[4];
    const float* b2 = (const float*)d_in[5];
    float*       out = (float*)d_out;

    int n = in_sizes[0];
    int E = in_sizes[1] / 2;
    int H = in_sizes[2];

    const int* src = ei;
    const int* dst = ei + E;

    // allow 200KB dynamic smem for the scatter kernel (idempotent host call)
    static bool attr_set = false;
    if (!attr_set) {
        cudaFuncSetAttribute(k_edge_smem,
                             cudaFuncAttributeMaxDynamicSharedMemorySize,
                             SMEM_BYTES);
        attr_set = true;
    }

    const int TB = 256;   // == MAXH (prep rider block requirement)
    int nt  = (n + 3) / 4;
    int nb4 = (nt + TB - 1) / TB;
    int et  = (E + 3) / 4;
    int eb  = (et + TB - 1) / TB;
    int pb  = 148;        // persistent scatter blocks (1 per SM)

    k_deg4<<<eb + 1, TB>>>(dst, E, W1, b1, W2, H);   // +1 prep rider block
    k_nodeA<<<nb4, TB>>>(x, n);
    k_edge_smem<<<pb, 1024, SMEM_BYTES>>>(src, dst, E);
    k_nodeB<<<nb4, TB>>>(H, n);
    k_edge_smem<<<pb, 1024, SMEM_BYTES>>>(src, dst, E);
    k_nodeC<<<nb4, TB>>>(out, b2, n);
}

// round 12
// speedup vs baseline: 1.0537x; 1.0537x over previous
#include <cuda_runtime.h>
#include <cuda_fp16.h>
#include <math_constants.h>

// ---------------------------------------------------------------------------
// 2-layer GCN collapsed to scalar graph ops (feature dims 1 -> H -> 1).
//   deg[v] = #in-edges + 1 ; dis[v] = rsqrt(deg[v])
//   s1[v]  = dis[v] * ( sum_{u->v} dis[u]*x[u] + dis[v]*x[v] )
//   t[v]   = PW(s1[v])  (piecewise-linear collapse of relu-MLP)
//   out[v] = dis[v] * ( sum_{u->v} dis[u]*t[u] + dis[v]*t[v] ) + b2
// All passes sit at the per-SM mem-instr accept floor (~1/cyc/SM):
//   deg 1.54 instr/edge, scatter 2.8 instr/edge. R11 proved LDS/LDG/REDG
// share that path, so the remaining lever is overlap: every kernel is PDL-
// launched; independent loads (edge indexes, x, PW tables) run in a pre-
// cudaGridDependencySynchronize prologue that overlaps the predecessor's
// tail. Index loads __ldcg (L2-resident), gathers fp16 via __ldg (L1).
// ---------------------------------------------------------------------------

#define MAXN 100352   // >= N_NODES (100000), multiple of 8
#define MAXH 256

__device__ float  g_deg[MAXN];    // zero at load; invariant: ==0 at call entry
__device__ float  g_dis[MAXN];
__device__ float  g_val[MAXN];    // fp32 message value (self-term use)
__device__ __half g_valh[MAXN];   // fp16 copy for L1-resident gathers
__device__ float  g_acc[MAXN];    // scatter accumulator (fp32)

__device__ float g_pw_c[MAXH];      // sorted breakpoints
__device__ float g_pw_A[MAXH + 1];  // segment slopes
__device__ float g_pw_B[MAXH + 1];  // segment intercepts

// ---- piecewise-linear table build (one 256-thread block) -------------------
__device__ void prep_block(const float* __restrict__ W1,
                           const float* __restrict__ b1,
                           const float* __restrict__ W2, int H) {
    __shared__ float sc[MAXH];
    __shared__ float sdA[MAXH], sdB[MAXH];
    __shared__ float sA[MAXH], sB[MAXH];
    __shared__ float s_base[2];

    int i = threadIdx.x;

    float w1 = (i < H) ? W1[i] : 0.0f;
    float bb = (i < H) ? b1[i] : 0.0f;
    float w2 = (i < H) ? W2[i] : 0.0f;
    float aa = w1 * w2;
    float cc = bb * w2;

    float key, dA, dB;
    float base_A = 0.0f, base_B = 0.0f;
    if (i < H && w1 > 0.0f) {
        key = -bb / w1; dA = aa;  dB = cc;
    } else if (i < H && w1 < 0.0f) {
        key = -bb / w1; dA = -aa; dB = -cc;
        base_A = aa; base_B = cc;
    } else {
        key = CUDART_INF_F; dA = 0.0f; dB = 0.0f;
        if (i < H && bb > 0.0f) base_B = cc;
    }
    sc[i] = key; sdA[i] = dA; sdB[i] = dB;
    sA[i] = base_A; sB[i] = base_B;
    __syncthreads();

    for (int off = MAXH / 2; off > 0; off >>= 1) {
        if (i < off) { sA[i] += sA[i + off]; sB[i] += sB[i + off]; }
        __syncthreads();
    }
    if (i == 0) { s_base[0] = sA[0]; s_base[1] = sB[0]; }
    __syncthreads();

    for (int k = 2; k <= MAXH; k <<= 1) {
        for (int j = k >> 1; j > 0; j >>= 1) {
            int ixj = i ^ j;
            if (ixj > i) {
                bool up = ((i & k) == 0);
                if ((sc[i] > sc[ixj]) == up) {
                    float tk = sc[i];  sc[i]  = sc[ixj];  sc[ixj]  = tk;
                    float ta = sdA[i]; sdA[i] = sdA[ixj]; sdA[ixj] = ta;
                    float tb = sdB[i]; sdB[i] = sdB[ixj]; sdB[ixj] = tb;
                }
            }
            __syncthreads();
        }
    }

    float pa = sdA[i], pb = sdB[i];
    sA[i] = pa; sB[i] = pb;
    __syncthreads();
    for (int off = 1; off < MAXH; off <<= 1) {
        float na = sA[i], nb = sB[i];
        if (i >= off) { na += sA[i - off]; nb += sB[i - off]; }
        __syncthreads();
        sA[i] = na; sB[i] = nb;
        __syncthreads();
    }

    g_pw_c[i] = sc[i];
    g_pw_A[i + 1] = s_base[0] + sA[i];
    g_pw_B[i + 1] = s_base[1] + sB[i];
    if (i == 0) { g_pw_A[0] = s_base[0]; g_pw_B[0] = s_base[1]; }
}

// ---- degree pass + prep rider (first kernel; sync is a no-op) --------------
__global__ void k_deg4(const int* __restrict__ dst, int E,
                       const float* __restrict__ W1,
                       const float* __restrict__ b1,
                       const float* __restrict__ W2, int H) {
    cudaTriggerProgrammaticLaunchCompletion();   // let nodeA's prologue start
    if (blockIdx.x == gridDim.x - 1) {           // prep rider block
        prep_block(W1, b1, W2, H);
        return;
    }
    int i = (blockIdx.x * blockDim.x + threadIdx.x) * 4;
    if (i + 3 < E) {
        int4 d = __ldcg(reinterpret_cast<const int4*>(dst + i));
        atomicAdd(&g_deg[d.x], 1.0f);
        atomicAdd(&g_deg[d.y], 1.0f);
        atomicAdd(&g_deg[d.z], 1.0f);
        atomicAdd(&g_deg[d.w], 1.0f);
    } else {
        for (; i < E; ++i) atomicAdd(&g_deg[__ldcg(dst + i)], 1.0f);
    }
}

// ---- scatter: prologue loads indexes, sync, then gather + atomic -----------
__global__ void k_edge4(const int* __restrict__ src,
                        const int* __restrict__ dst, int E) {
    int i = (blockIdx.x * blockDim.x + threadIdx.x) * 4;
    int4 s, d;
    bool full = (i + 3 < E);
    if (full) {                                  // independent prologue
        s = __ldcg(reinterpret_cast<const int4*>(src + i));
        d = __ldcg(reinterpret_cast<const int4*>(dst + i));
    }
    cudaGridDependencySynchronize();             // wait predecessor complete
    cudaTriggerProgrammaticLaunchCompletion();   // successor may launch
    if (full) {
        float v0 = __half2float(__ldg(&g_valh[s.x]));
        float v1 = __half2float(__ldg(&g_valh[s.y]));
        float v2 = __half2float(__ldg(&g_valh[s.z]));
        float v3 = __half2float(__ldg(&g_valh[s.w]));
        atomicAdd(&g_acc[d.x], v0);
        atomicAdd(&g_acc[d.y], v1);
        atomicAdd(&g_acc[d.z], v2);
        atomicAdd(&g_acc[d.w], v3);
    } else {
        for (; i < E; ++i)
            atomicAdd(&g_acc[__ldcg(dst + i)],
                      __half2float(__ldg(&g_valh[__ldcg(src + i)])));
    }
}

// ---- node kernels, 4 nodes/thread -------------------------------------------
__global__ void k_nodeA(const float* __restrict__ x, int n) {
    int t = blockIdx.x * blockDim.x + threadIdx.x;
    int v = t * 4;
    float4 xx = make_float4(0.f, 0.f, 0.f, 0.f);
    bool full = (v + 3 < n);
    if (full) xx = *reinterpret_cast<const float4*>(&x[v]);  // prologue
    cudaGridDependencySynchronize();
    cudaTriggerProgrammaticLaunchCompletion();
    if (full) {
        float4 dg = *reinterpret_cast<float4*>(&g_deg[v]);
        float4 d, val;
        d.x = rsqrtf(dg.x + 1.0f); d.y = rsqrtf(dg.y + 1.0f);
        d.z = rsqrtf(dg.z + 1.0f); d.w = rsqrtf(dg.w + 1.0f);
        val.x = d.x * xx.x; val.y = d.y * xx.y;
        val.z = d.z * xx.z; val.w = d.w * xx.w;
        *reinterpret_cast<float4*>(&g_deg[v]) = make_float4(0.f, 0.f, 0.f, 0.f);
        *reinterpret_cast<float4*>(&g_dis[v]) = d;
        *reinterpret_cast<float4*>(&g_val[v]) = val;
        *reinterpret_cast<__half2*>(&g_valh[v])     = __floats2half2_rn(val.x, val.y);
        *reinterpret_cast<__half2*>(&g_valh[v + 2]) = __floats2half2_rn(val.z, val.w);
        *reinterpret_cast<float4*>(&g_acc[v]) = make_float4(0.f, 0.f, 0.f, 0.f);
    } else {
        for (; v < n; ++v) {
            float d = rsqrtf(g_deg[v] + 1.0f);
            g_deg[v] = 0.0f;
            float val = d * x[v];
            g_dis[v] = d;
            g_val[v] = val;
            g_valh[v] = __float2half_rn(val);
            g_acc[v] = 0.0f;
        }
    }
}

// nodeB: PW tables staged in prologue (written 3 kernels upstream — complete
// before this kernel's prologue can start, by PDL trigger-after-sync order).
__global__ void k_nodeB(int H, int n) {
    __shared__ float sc[MAXH], sA[MAXH + 1], sB[MAXH + 1];
    for (int k = threadIdx.x; k < MAXH; k += blockDim.x) {
        sc[k] = g_pw_c[k];
        sA[k] = g_pw_A[k];
        sB[k] = g_pw_B[k];
    }
    if (threadIdx.x == 0) { sA[MAXH] = g_pw_A[MAXH]; sB[MAXH] = g_pw_B[MAXH]; }
    __syncthreads();
    cudaGridDependencySynchronize();
    cudaTriggerProgrammaticLaunchCompletion();
    int t = blockIdx.x * blockDim.x + threadIdx.x;
    int v = t * 4;
    if (v + 3 < n) {
        float4 d   = *reinterpret_cast<float4*>(&g_dis[v]);
        float4 ac  = *reinterpret_cast<float4*>(&g_acc[v]);
        float4 vl  = *reinterpret_cast<float4*>(&g_val[v]);
        float s[4], dd[4];
        dd[0] = d.x; dd[1] = d.y; dd[2] = d.z; dd[3] = d.w;
        s[0] = d.x * (ac.x + vl.x); s[1] = d.y * (ac.y + vl.y);
        s[2] = d.z * (ac.z + vl.z); s[3] = d.w * (ac.w + vl.w);
        int lo[4] = {0, 0, 0, 0}, hi[4] = {MAXH, MAXH, MAXH, MAXH};
        #pragma unroll
        for (int step = 0; step < 8; ++step) {
            #pragma unroll
            for (int j = 0; j < 4; ++j) {
                int mid = (lo[j] + hi[j]) >> 1;
                if (sc[mid] <= s[j]) lo[j] = mid + 1; else hi[j] = mid;
            }
        }
        float4 val;
        val.x = dd[0] * fmaf(sA[lo[0]], s[0], sB[lo[0]]);
        val.y = dd[1] * fmaf(sA[lo[1]], s[1], sB[lo[1]]);
        val.z = dd[2] * fmaf(sA[lo[2]], s[2], sB[lo[2]]);
        val.w = dd[3] * fmaf(sA[lo[3]], s[3], sB[lo[3]]);
        *reinterpret_cast<float4*>(&g_val[v]) = val;
        *reinterpret_cast<__half2*>(&g_valh[v])     = __floats2half2_rn(val.x, val.y);
        *reinterpret_cast<__half2*>(&g_valh[v + 2]) = __floats2half2_rn(val.z, val.w);
        *reinterpret_cast<float4*>(&g_acc[v]) = make_float4(0.f, 0.f, 0.f, 0.f);
    } else {
        for (; v < n; ++v) {
            float d = g_dis[v];
            float s = d * (g_acc[v] + g_val[v]);
            int lo = 0, hi2 = MAXH;
            #pragma unroll
            for (int step = 0; step < 8; ++step) {
                int mid = (lo + hi2) >> 1;
                if (sc[mid] <= s) lo = mid + 1; else hi2 = mid;
            }
            float val = d * fmaf(sA[lo], s, sB[lo]);
            g_val[v] = val;
            g_valh[v] = __float2half_rn(val);
            g_acc[v] = 0.0f;
        }
    }
}

__global__ void k_nodeC(float* __restrict__ out, const float* __restrict__ b2,
                        int n) {
    float bias = __ldg(b2);                       // independent prologue
    cudaGridDependencySynchronize();
    int t = blockIdx.x * blockDim.x + threadIdx.x;
    int v = t * 4;
    if (v + 3 < n) {
        float4 d  = *reinterpret_cast<float4*>(&g_dis[v]);
        float4 ac = *reinterpret_cast<float4*>(&g_acc[v]);
        float4 vl = *reinterpret_cast<float4*>(&g_val[v]);
        float4 o;
        o.x = fmaf(d.x, ac.x + vl.x, bias);
        o.y = fmaf(d.y, ac.y + vl.y, bias);
        o.z = fmaf(d.z, ac.z + vl.z, bias);
        o.w = fmaf(d.w, ac.w + vl.w, bias);
        *reinterpret_cast<float4*>(&out[v]) = o;
    } else {
        for (; v < n; ++v)
            out[v] = fmaf(g_dis[v], g_acc[v] + g_val[v], bias);
    }
}

// ---- host: PDL launches ------------------------------------------------------
static void launch_pdl(void* func, dim3 grid, dim3 block, void** args) {
    cudaLaunchConfig_t cfg = {};
    cfg.gridDim = grid;
    cfg.blockDim = block;
    cfg.dynamicSmemBytes = 0;
    cfg.stream = 0;
    cudaLaunchAttribute attr[1];
    attr[0].id = cudaLaunchAttributeProgrammaticStreamSerialization;
    attr[0].val.programmaticStreamSerializationAllowed = 1;
    cfg.attrs = attr;
    cfg.numAttrs = 1;
    cudaLaunchKernelExC(&cfg, func, args);
}

extern "C" void kernel_launch(void* const* d_in, const int* in_sizes, int n_in,
                              void* d_out, int out_size) {
    const float* x  = (const float*)d_in[0];
    const int*   ei = (const int*)d_in[1];     // int32 edge indices
    const float* W1 = (const float*)d_in[2];
    const float* b1 = (const float*)d_in[3];
    const float* W2 = (const float*)d_in[4];
    const float* b2 = (const float*)d_in[5];
    float*       out = (float*)d_out;

    int n = in_sizes[0];
    int E = in_sizes[1] / 2;
    int H = in_sizes[2];

    const int* src = ei;
    const int* dst = ei + E;

    const int TB = 256;   // == MAXH (prep rider block requirement)
    int nt  = (n + 3) / 4;
    int nb4 = (nt + TB - 1) / TB;
    int et  = (E + 3) / 4;
    int eb  = (et + TB - 1) / TB;

    {   // deg + prep rider
        void* args[] = {(void*)&dst, (void*)&E, (void*)&W1, (void*)&b1,
                        (void*)&W2, (void*)&H};
        launch_pdl((void*)k_deg4, dim3(eb + 1), dim3(TB), args);
    }
    {   // nodeA
        void* args[] = {(void*)&x, (void*)&n};
        launch_pdl((void*)k_nodeA, dim3(nb4), dim3(TB), args);
    }
    {   // scatter 1
        void* args[] = {(void*)&src, (void*)&dst, (void*)&E};
        launch_pdl((void*)k_edge4, dim3(eb), dim3(TB), args);
    }
    {   // nodeB
        void* args[] = {(void*)&H, (void*)&n};
        launch_pdl((void*)k_nodeB, dim3(nb4), dim3(TB), args);
    }
    {   // scatter 2
        void* args[] = {(void*)&src, (void*)&dst, (void*)&E};
        launch_pdl((void*)k_edge4, dim3(eb), dim3(TB), args);
    }
    {   // nodeC
        void* args[] = {(void*)&out, (void*)&b2, (void*)&n};
        launch_pdl((void*)k_nodeC, dim3(nb4), dim3(TB), args);
    }
}